// round 7
// baseline (speedup 1.0000x reference)
#include <cuda_runtime.h>
#include <cstdint>

// Embedding gather, engine-split version:
//   reads  : LDG.128 (L1tex path)
//   writes : STS -> cp.async.bulk smem->global (bulk/TMA engine)
// Each engine carries ~16.8 MB instead of one engine carrying all 33 MB.
//
// CTA = 256 threads, 4 rows (tokens), 16 KB smem stage. Grid = 1024 (one wave).
// Loads are issued as ordered asm volatile so all 4 LDG.128 per thread are in
// flight before the first STS (ptxas cannot reorder/serialize them).

static constexpr int ROW_F4     = 256;   // float4 per 4 KB row
static constexpr int ROW_BYTES  = 4096;
static constexpr int ROWS_PER_CTA = 4;
static constexpr int STAGE_BYTES = ROWS_PER_CTA * ROW_BYTES;  // 16 KB

__device__ __forceinline__ uint32_t smem_u32(const void* p) {
    uint32_t a;
    asm("{ .reg .u64 t; cvta.to.shared.u64 t, %1; cvt.u32.u64 %0, t; }"
        : "=r"(a) : "l"(p));
    return a;
}

__global__ void __launch_bounds__(256)
embed_gather_split(const int* __restrict__ ids,
                   const float4* __restrict__ emb,
                   char* __restrict__ out,
                   int n_tokens)
{
    __shared__ alignas(128) char buf[STAGE_BYTES];

    const int tid  = threadIdx.x;
    const int base = blockIdx.x * ROWS_PER_CTA;

    // ids (guard only the degenerate tail; 4096 % 4 == 0 for this problem)
    int id0 = ids[min(base + 0, n_tokens - 1)];
    int id1 = ids[min(base + 1, n_tokens - 1)];
    int id2 = ids[min(base + 2, n_tokens - 1)];
    int id3 = ids[min(base + 3, n_tokens - 1)];

    const float4* s0 = emb + (size_t)id0 * ROW_F4 + tid;
    const float4* s1 = emb + (size_t)id1 * ROW_F4 + tid;
    const float4* s2 = emb + (size_t)id2 * ROW_F4 + tid;
    const float4* s3 = emb + (size_t)id3 * ROW_F4 + tid;

    // Ordered asm: all 4 LDG.128 issue before any STS (true MLP=4/thread).
    float a0,a1,a2,a3, b0,b1,b2,b3, c0,c1,c2,c3, d0,d1,d2,d3;
    asm volatile("ld.global.nc.v4.f32 {%0,%1,%2,%3}, [%4];"
                 : "=f"(a0),"=f"(a1),"=f"(a2),"=f"(a3) : "l"(s0));
    asm volatile("ld.global.nc.v4.f32 {%0,%1,%2,%3}, [%4];"
                 : "=f"(b0),"=f"(b1),"=f"(b2),"=f"(b3) : "l"(s1));
    asm volatile("ld.global.nc.v4.f32 {%0,%1,%2,%3}, [%4];"
                 : "=f"(c0),"=f"(c1),"=f"(c2),"=f"(c3) : "l"(s2));
    asm volatile("ld.global.nc.v4.f32 {%0,%1,%2,%3}, [%4];"
                 : "=f"(d0),"=f"(d1),"=f"(d2),"=f"(d3) : "l"(s3));

    const uint32_t sb = smem_u32(buf) + tid * 16;
    asm volatile("st.shared.v4.f32 [%0], {%1,%2,%3,%4};"
                 :: "r"(sb + 0 * ROW_BYTES), "f"(a0),"f"(a1),"f"(a2),"f"(a3) : "memory");
    asm volatile("st.shared.v4.f32 [%0], {%1,%2,%3,%4};"
                 :: "r"(sb + 1 * ROW_BYTES), "f"(b0),"f"(b1),"f"(b2),"f"(b3) : "memory");
    asm volatile("st.shared.v4.f32 [%0], {%1,%2,%3,%4};"
                 :: "r"(sb + 2 * ROW_BYTES), "f"(c0),"f"(c1),"f"(c2),"f"(c3) : "memory");
    asm volatile("st.shared.v4.f32 [%0], {%1,%2,%3,%4};"
                 :: "r"(sb + 3 * ROW_BYTES), "f"(d0),"f"(d1),"f"(d2),"f"(d3) : "memory");

    __syncthreads();

    // Bulk stores: 4 lanes, one 4 KB row each, on the async engine.
    if (tid < ROWS_PER_CTA) {
        int token = base + tid;
        if (token < n_tokens) {
            asm volatile("fence.proxy.async.shared::cta;" ::: "memory");
            char* dst = out + (size_t)token * ROW_BYTES;
            uint32_t src = smem_u32(buf) + tid * ROW_BYTES;
            asm volatile(
                "cp.async.bulk.global.shared::cta.bulk_group [%0], [%1], %2;"
                :: "l"(dst), "r"(src), "r"((uint32_t)ROW_BYTES) : "memory");
            asm volatile("cp.async.bulk.commit_group;" ::: "memory");
            asm volatile("cp.async.bulk.wait_group.read 0;" ::: "memory");
        }
    }
}

extern "C" void kernel_launch(void* const* d_in, const int* in_sizes, int n_in,
                              void* d_out, int out_size)
{
    const int*    ids = (const int*)d_in[0];
    const float4* emb = (const float4*)d_in[1];
    char*         out = (char*)d_out;

    int n_tokens = in_sizes[0];   // 4096
    int grid = (n_tokens + ROWS_PER_CTA - 1) / ROWS_PER_CTA;  // 1024 — one wave
    embed_gather_split<<<grid, 256>>>(ids, emb, out, n_tokens);
}

// round 8
// speedup vs baseline: 1.2581x; 1.2581x over previous
#include <cuda_runtime.h>
#include <cstdint>

// Embedding gather, software-pipelined:
//   out[token, :] = embedding[input_ids[token], :]
//
// Each CTA (256 threads) handles 8 tokens. All 8 ids are hoisted first
// (one 32-byte line, broadcast) so the 8 row loads become mutually
// independent. A depth-4 rolling register ring then overlaps loads of
// rows j+4 with stores of row j: the id->row DRAM dependency chain is
// exposed exactly ONCE per CTA, everything after runs at issue rate.
// grid = 512 CTAs -> single wave, ~3.5 CTAs/SM, MLP_p1 = 4 (below the
// cross-CTA L1tex-queue contention knee oe*MLP ~ 16).

static constexpr int ROW_F4       = 256;  // float4 per 4 KB row
static constexpr int TOKENS_PER_CTA = 8;
static constexpr int DEPTH        = 4;

__global__ void __launch_bounds__(256)
embed_gather_pipe(const int* __restrict__ ids,
                  const float4* __restrict__ emb,
                  float4* __restrict__ out,
                  int n_tokens)
{
    const int tid  = threadIdx.x;
    const int base = blockIdx.x * TOKENS_PER_CTA;

    // Hoist all ids (independent loads, same 32B line, broadcast).
    int id[TOKENS_PER_CTA];
#pragma unroll
    for (int j = 0; j < TOKENS_PER_CTA; j++)
        id[j] = ids[base + j];

    float4* __restrict__ dst = out + (size_t)base * ROW_F4 + tid;

    // Prologue: fill the depth-4 ring (4 independent row loads).
    float4 v[DEPTH];
#pragma unroll
    for (int j = 0; j < DEPTH; j++)
        v[j] = emb[(size_t)id[j] * ROW_F4 + tid];

    // Steady state: store row j, immediately refill slot with row j+4.
#pragma unroll
    for (int j = 0; j < TOKENS_PER_CTA; j++) {
        dst[(size_t)j * ROW_F4] = v[j & (DEPTH - 1)];
        if (j + DEPTH < TOKENS_PER_CTA)
            v[j & (DEPTH - 1)] = emb[(size_t)id[j + DEPTH] * ROW_F4 + tid];
    }
}

extern "C" void kernel_launch(void* const* d_in, const int* in_sizes, int n_in,
                              void* d_out, int out_size)
{
    const int*    ids = (const int*)d_in[0];
    const float4* emb = (const float4*)d_in[1];
    float4*       out = (float4*)d_out;

    int n_tokens = in_sizes[0];   // 4096
    int grid = (n_tokens + TOKENS_PER_CTA - 1) / TOKENS_PER_CTA;  // 512
    embed_gather_pipe<<<grid, 256>>>(ids, emb, out, n_tokens);
}

// round 9
// speedup vs baseline: 1.3048x; 1.0372x over previous
#include <cuda_runtime.h>
#include <cstdint>

// Embedding gather: out[token, :] = embedding[input_ids[token], :]
// input_ids: [4096] i32, embedding: [32000,1024] f32, out: [4096,1024] f32
//
// Best-known geometry (R5): 1024 CTAs x 256 threads, single resident wave,
// 4 tokens/CTA, 4 independent row LDG.128 per thread. Micro-tuned:
//  - the 4 token ids load as ONE int4 (16 B aligned) -> dependent chain head
//    is a single transaction instead of 4
//  - rows via ld.global.nc (__ldg)
//  - stores via st.global.cs (evict-first: output never re-read, keeps L2
//    capacity for gathered rows / duplicate-token hits)

static constexpr int ROW_F4        = 256;  // float4 per 4 KB row
static constexpr int TOKENS_PER_CTA = 4;

__device__ __forceinline__ void stcs(float4* p, float4 v) {
    asm volatile("st.global.cs.v4.f32 [%0], {%1,%2,%3,%4};"
                 :: "l"(p), "f"(v.x), "f"(v.y), "f"(v.z), "f"(v.w) : "memory");
}

__global__ void __launch_bounds__(256)
embed_gather_kernel(const int4* __restrict__ ids4,
                    const float4* __restrict__ emb,
                    float4* __restrict__ out,
                    int n_tokens)
{
    const int tid  = threadIdx.x;
    const int base = blockIdx.x * TOKENS_PER_CTA;

    // One 16-byte load fetches all 4 token ids (broadcast across the CTA).
    int4 id = ids4[blockIdx.x];

    // 4 independent row loads (different rows -> true MLP=4).
    float4 v0 = __ldg(emb + (size_t)id.x * ROW_F4 + tid);
    float4 v1 = __ldg(emb + (size_t)id.y * ROW_F4 + tid);
    float4 v2 = __ldg(emb + (size_t)id.z * ROW_F4 + tid);
    float4 v3 = __ldg(emb + (size_t)id.w * ROW_F4 + tid);

    float4* dst = out + (size_t)base * ROW_F4 + tid;
    stcs(dst + 0 * ROW_F4, v0);
    stcs(dst + 1 * ROW_F4, v1);
    stcs(dst + 2 * ROW_F4, v2);
    stcs(dst + 3 * ROW_F4, v3);
}

extern "C" void kernel_launch(void* const* d_in, const int* in_sizes, int n_in,
                              void* d_out, int out_size)
{
    const int4*   ids4 = (const int4*)d_in[0];
    const float4* emb  = (const float4*)d_in[1];
    float4*       out  = (float4*)d_out;

    int n_tokens = in_sizes[0];   // 4096 (divisible by 4)
    int grid = n_tokens / TOKENS_PER_CTA;   // 1024 — single resident wave
    embed_gather_kernel<<<grid, 256>>>(ids4, emb, out, n_tokens);
}